// round 1
// baseline (speedup 1.0000x reference)
#include <cuda_runtime.h>
#include <cuda_fp16.h>

#define SEQ  256
#define VOC  96
#define DEND (SEQ * VOC)          // 24576 dendrites
#define ZROW DEND                 // extra all-zero row for masked positions
#define ZOFF (DEND * (VOC / 2))   // half2 offset of the zero row

// fp16 transposed log-weight table: T[d][v] = log(max(2*sigmoid(raw[v][d]), 1e-8))
// (DEND+1) rows of VOC halves; last row is zeros. ~4.7 MB -> L2 resident.
__device__ __half g_logw[(DEND + 1) * VOC];

// ---------------------------------------------------------------------------
// Kernel A: fused sigmoid/log + transpose (coalesced both sides via smem tile)
// grid (768, 3), block (32, 8)
// ---------------------------------------------------------------------------
__global__ void prep_kernel(const float* __restrict__ raw) {
    __shared__ float tile[32][33];
    const int d0 = blockIdx.x * 32;
    const int v0 = blockIdx.y * 32;
    const int tx = threadIdx.x, ty = threadIdx.y;

    #pragma unroll
    for (int i = ty; i < 32; i += 8) {
        float x = raw[(v0 + i) * DEND + (d0 + tx)];
        // 2*sigmoid(x) = 2 / (1 + exp(-x));  x in (-1,1) so no overflow paths
        float w = 2.0f * __frcp_rn(1.0f + __expf(-x));
        w = fmaxf(w, 1e-8f);
        tile[i][tx] = __logf(w);
    }
    __syncthreads();
    #pragma unroll
    for (int i = ty; i < 32; i += 8) {
        g_logw[(d0 + i) * VOC + (v0 + tx)] = __float2half_rn(tile[tx][i]);
    }
    // zero row for masked (char==0) positions
    if (blockIdx.x == 0 && blockIdx.y == 0 && ty == 0) {
        #pragma unroll
        for (int k = tx; k < VOC; k += 32)
            g_logw[ZROW * VOC + k] = __float2half_rn(0.0f);
    }
}

// ---------------------------------------------------------------------------
// Kernel B: per-sample gather + reduce.
// 96 threads / block, 2 samples / block: threads [0,48) -> sample 0,
// [48,96) -> sample 1; each thread owns a half2 (two vocab entries).
// ---------------------------------------------------------------------------
__global__ void gather_kernel(const int* __restrict__ chars,
                              float* __restrict__ out,
                              int batch) {
    __shared__ int offs[2][SEQ];   // half2-unit offsets into g_logw per position

    const int t  = threadIdx.x;    // 0..95
    const int b0 = blockIdx.x * 2;

    // Build the offset table for both samples (branch-free gather targets).
    for (int i = t; i < 2 * SEQ; i += 96) {
        const int smp = i >> 8;
        const int s   = i & (SEQ - 1);
        int off = ZOFF;
        if (b0 + smp < batch) {
            const int c = chars[(b0 + smp) * SEQ + s];
            const int dend = (c > 0) ? (s * VOC + c - 1) : ZROW;
            off = dend * (VOC / 2);
        }
        offs[smp][s] = off;
    }
    __syncthreads();

    const int who  = t / 48;
    const int pair = t - who * 48;          // which half2 of the 48
    if (b0 + who >= batch) return;

    const __half2* __restrict__ base = (const __half2*)g_logw;
    const int* __restrict__ o = offs[who];

    float a0x = 0.f, a0y = 0.f, a1x = 0.f, a1y = 0.f;
    float a2x = 0.f, a2y = 0.f, a3x = 0.f, a3y = 0.f;
    int nact = 0;

    #pragma unroll 2
    for (int s = 0; s < SEQ; s += 4) {
        const int o0 = o[s], o1 = o[s + 1], o2 = o[s + 2], o3 = o[s + 3];
        const float2 f0 = __half22float2(base[o0 + pair]);
        const float2 f1 = __half22float2(base[o1 + pair]);
        const float2 f2 = __half22float2(base[o2 + pair]);
        const float2 f3 = __half22float2(base[o3 + pair]);
        nact += (o0 != ZOFF) + (o1 != ZOFF) + (o2 != ZOFF) + (o3 != ZOFF);
        a0x += f0.x; a0y += f0.y;
        a1x += f1.x; a1y += f1.y;
        a2x += f2.x; a2y += f2.y;
        a3x += f3.x; a3y += f3.y;
    }

    const float sx = (a0x + a1x) + (a2x + a3x);
    const float sy = (a0y + a1y) + (a2y + a3y);
    const float inv = __frcp_rn((float)max(nact, 1));

    out[(b0 + who) * VOC + 2 * pair]     = __expf(sx * inv);
    out[(b0 + who) * VOC + 2 * pair + 1] = __expf(sy * inv);
}

// ---------------------------------------------------------------------------
extern "C" void kernel_launch(void* const* d_in, const int* in_sizes, int n_in,
                              void* d_out, int out_size) {
    const int*   chars = (const int*)d_in[0];     // (B, 256) int32
    const float* raw   = (const float*)d_in[1];   // (96, 24576) float32
    float*       out   = (float*)d_out;           // (B, 96) float32

    const int batch = in_sizes[0] / SEQ;

    dim3 pgrid(DEND / 32, VOC / 32);              // (768, 3)
    dim3 pblk(32, 8);
    prep_kernel<<<pgrid, pblk>>>(raw);

    const int nblk = (batch + 1) / 2;
    gather_kernel<<<nblk, 96>>>(chars, out, batch);
}

// round 2
// speedup vs baseline: 1.3266x; 1.3266x over previous
#include <cuda_runtime.h>
#include <cuda_fp16.h>

#define SEQ   256
#define VOC   96
#define DEND  (SEQ * VOC)            // 24576 dendrites
#define ZROW  DEND                   // all-zero row for masked positions
#define LANES 24                     // uint2 (4 halves) per lane: 24*8B = 192B row
#define CHUNKS 16
#define CPOS  (SEQ / CHUNKS)         // 16 positions per chunk
#define ROWU2 (VOC / 4)              // 24 uint2 per row
#define ZOFF2 (ZROW * ROWU2)

// fp16 transposed log-weight table: T[d][v] = log(max(2*sigmoid(raw[v][d]), 1e-8))
// (DEND+1) rows of VOC halves; last row zeros. ~4.7 MB -> L2 resident.
__device__ __half g_logw[(DEND + 1) * VOC];

// ---------------------------------------------------------------------------
// Kernel A: fused sigmoid/log + transpose (coalesced both sides via smem tile)
// ---------------------------------------------------------------------------
__global__ void prep_kernel(const float* __restrict__ raw) {
    __shared__ float tile[32][33];
    const int d0 = blockIdx.x * 32;
    const int v0 = blockIdx.y * 32;
    const int tx = threadIdx.x, ty = threadIdx.y;

    #pragma unroll
    for (int i = ty; i < 32; i += 8) {
        float x = raw[(v0 + i) * DEND + (d0 + tx)];
        float w = 2.0f * __frcp_rn(1.0f + __expf(-x));
        w = fmaxf(w, 1e-8f);
        tile[i][tx] = __logf(w);
    }
    __syncthreads();
    #pragma unroll
    for (int i = ty; i < 32; i += 8) {
        g_logw[(d0 + i) * VOC + (v0 + tx)] = __float2half_rn(tile[tx][i]);
    }
    if (blockIdx.x == 0 && blockIdx.y == 0 && ty == 0) {
        #pragma unroll
        for (int k = tx; k < VOC; k += 32)
            g_logw[ZROW * VOC + k] = __float2half_rn(0.0f);
    }
}

// ---------------------------------------------------------------------------
// Kernel B: one sample per block, 384 threads.
// thread t: chunk = t/24 (16 seq positions), lane = t%24 (4 vocab entries).
// Stage 1: per-thread gather+sum over 16 positions (8B loads).
// Stage 2: smem reduce over 16 chunks, exp, float4 store.
// ---------------------------------------------------------------------------
__global__ void __launch_bounds__(LANES * CHUNKS)
gather_kernel(const int* __restrict__ chars,
              float* __restrict__ out) {
    __shared__ int    offs[SEQ];                 // uint2-unit row offsets
    __shared__ float4 part[CHUNKS][LANES];
    __shared__ int    cnts[CHUNKS];

    const int b = blockIdx.x;
    const int t = threadIdx.x;                   // 0..383

    if (t < SEQ) {
        const int c = chars[b * SEQ + t];
        const int dend = (c > 0) ? (t * VOC + c - 1) : ZROW;
        offs[t] = dend * ROWU2;
    }
    __syncthreads();

    const int lane  = t % LANES;
    const int chunk = t / LANES;
    const int s0    = chunk * CPOS;
    const uint2* __restrict__ base = (const uint2*)g_logw;

    float ax = 0.f, ay = 0.f, az = 0.f, aw = 0.f;
    float bx = 0.f, by = 0.f, bz = 0.f, bw = 0.f;
    int nact = 0;

    #pragma unroll
    for (int i = 0; i < CPOS; i += 4) {
        const int o0 = offs[s0 + i];
        const int o1 = offs[s0 + i + 1];
        const int o2 = offs[s0 + i + 2];
        const int o3 = offs[s0 + i + 3];
        const uint2 u0 = base[o0 + lane];
        const uint2 u1 = base[o1 + lane];
        const uint2 u2 = base[o2 + lane];
        const uint2 u3 = base[o3 + lane];
        nact += (o0 != ZOFF2) + (o1 != ZOFF2) + (o2 != ZOFF2) + (o3 != ZOFF2);

        float2 p, q;
        p = __half22float2(*(const __half2*)&u0.x);
        q = __half22float2(*(const __half2*)&u0.y);
        ax += p.x; ay += p.y; az += q.x; aw += q.y;
        p = __half22float2(*(const __half2*)&u1.x);
        q = __half22float2(*(const __half2*)&u1.y);
        bx += p.x; by += p.y; bz += q.x; bw += q.y;
        p = __half22float2(*(const __half2*)&u2.x);
        q = __half22float2(*(const __half2*)&u2.y);
        ax += p.x; ay += p.y; az += q.x; aw += q.y;
        p = __half22float2(*(const __half2*)&u3.x);
        q = __half22float2(*(const __half2*)&u3.y);
        bx += p.x; by += p.y; bz += q.x; bw += q.y;
    }

    part[chunk][lane] = make_float4(ax + bx, ay + by, az + bz, aw + bw);
    if (lane == 0) cnts[chunk] = nact;
    __syncthreads();

    if (t < LANES) {
        float sx = 0.f, sy = 0.f, sz = 0.f, sw = 0.f;
        int n = 0;
        #pragma unroll
        for (int k = 0; k < CHUNKS; k++) {
            const float4 v = part[k][t];
            sx += v.x; sy += v.y; sz += v.z; sw += v.w;
            n += cnts[k];
        }
        const float inv = __frcp_rn((float)max(n, 1));
        float4 r;
        r.x = __expf(sx * inv);
        r.y = __expf(sy * inv);
        r.z = __expf(sz * inv);
        r.w = __expf(sw * inv);
        ((float4*)(out + b * VOC))[t] = r;
    }
}

// ---------------------------------------------------------------------------
extern "C" void kernel_launch(void* const* d_in, const int* in_sizes, int n_in,
                              void* d_out, int out_size) {
    const int*   chars = (const int*)d_in[0];     // (B, 256) int32
    const float* raw   = (const float*)d_in[1];   // (96, 24576) float32
    float*       out   = (float*)d_out;           // (B, 96) float32

    const int batch = in_sizes[0] / SEQ;

    dim3 pgrid(DEND / 32, VOC / 32);              // (768, 3)
    dim3 pblk(32, 8);
    prep_kernel<<<pgrid, pblk>>>(raw);

    gather_kernel<<<batch, LANES * CHUNKS>>>(chars, out);
}